// round 4
// baseline (speedup 1.0000x reference)
#include <cuda_runtime.h>
#include <math.h>

#define B_ROWS 16384
#define NCLS   1000
#define KDIM   1000
#define EPS    0.1f

#define BM 128
#define BN 128
#define BK 8
#define TM 8
#define TN 8
#define LDS_STRIDE 132   // 128 + 4 pad to kill store bank conflicts

// Scratch (allocation-free rule: __device__ globals)
__device__ float g_S[(size_t)B_ROWS * NCLS];   // logits S[b,n] = 2*dot - csum[n]
__device__ float g_csum[NCLS];
__device__ float g_row[B_ROWS];
__device__ int   g_labmode;                    // 1 = int32 labels, 0 = int64 labels

// ---------------------------------------------------------------------------
// Detect label dtype: if labels are int64 (little-endian), every odd int32
// word is the hi word of a value in [0,1000) -> all zero. If int32, the odd
// words are actual labels; 8192 of them all being zero has ~nil probability.
// Only scans the first 16384 int32s, which is in-bounds for either dtype.
// ---------------------------------------------------------------------------
__global__ void detect_kernel(const int* __restrict__ l32) {
    __shared__ int s_any;
    if (threadIdx.x == 0) s_any = 0;
    __syncthreads();
    int local = 0;
    for (int i = threadIdx.x; i < B_ROWS / 2; i += blockDim.x)
        local |= l32[2 * i + 1];
    if (local) atomicOr(&s_any, 1);
    __syncthreads();
    if (threadIdx.x == 0) g_labmode = (s_any != 0) ? 1 : 0;
}

// ---------------------------------------------------------------------------
// csum[n] = sum_d code_book[n, d]   (one warp per codebook row)
// ---------------------------------------------------------------------------
__global__ void csum_kernel(const float* __restrict__ Cb) {
    int warp = (blockIdx.x * blockDim.x + threadIdx.x) >> 5;
    int lane = threadIdx.x & 31;
    if (warp >= NCLS) return;
    const float* r = Cb + (size_t)warp * KDIM;
    float s = 0.f;
    for (int i = lane; i < KDIM; i += 32) s += r[i];
    #pragma unroll
    for (int off = 16; off > 0; off >>= 1)
        s += __shfl_xor_sync(0xFFFFFFFFu, s, off);
    if (lane == 0) g_csum[warp] = s;
}

// ---------------------------------------------------------------------------
// Tiled SGEMM: S[b,n] = 2 * sum_d A[b,d]*C[n,d] - csum[n]
// 128x128 tile, BK=8, 256 threads, 8x8 per-thread microtile.
// Both operands are K-major (row-major with K contiguous) -> "NT" gemm.
// ---------------------------------------------------------------------------
__global__ void __launch_bounds__(256, 2)
gemm_kernel(const float* __restrict__ A, const float* __restrict__ Cb) {
    __shared__ float As[BK][LDS_STRIDE];
    __shared__ float Bs[BK][LDS_STRIDE];

    const int tid = threadIdx.x;
    const int m0  = blockIdx.y * BM;
    const int n0  = blockIdx.x * BN;
    const int tm  = tid >> 4;    // 0..15
    const int tn  = tid & 15;    // 0..15

    // Global load mapping: thread loads one float4 of A and one of C per k-step
    const int lr = tid >> 1;           // 0..127 : row within tile
    const int lk = (tid & 1) * 4;      // 0 or 4 : k offset within BK
    const float* Ap = A  + (size_t)(m0 + lr) * KDIM + lk;
    const bool bvalid = (n0 + lr) < NCLS;
    const float* Bp = Cb + (size_t)(bvalid ? (n0 + lr) : 0) * KDIM + lk;

    float acc[TM][TN];
    #pragma unroll
    for (int i = 0; i < TM; i++)
        #pragma unroll
        for (int j = 0; j < TN; j++) acc[i][j] = 0.f;

    for (int k0 = 0; k0 < KDIM; k0 += BK) {
        float4 a4 = *reinterpret_cast<const float4*>(Ap + k0);
        float4 b4 = bvalid ? *reinterpret_cast<const float4*>(Bp + k0)
                           : make_float4(0.f, 0.f, 0.f, 0.f);
        __syncthreads();
        As[lk + 0][lr] = a4.x; As[lk + 1][lr] = a4.y;
        As[lk + 2][lr] = a4.z; As[lk + 3][lr] = a4.w;
        Bs[lk + 0][lr] = b4.x; Bs[lk + 1][lr] = b4.y;
        Bs[lk + 2][lr] = b4.z; Bs[lk + 3][lr] = b4.w;
        __syncthreads();

        #pragma unroll
        for (int k = 0; k < BK; k++) {
            const float4* ap = reinterpret_cast<const float4*>(&As[k][tm * TM]);
            const float4* bp = reinterpret_cast<const float4*>(&Bs[k][tn * TN]);
            float4 a0 = ap[0], a1 = ap[1];
            float4 b0 = bp[0], b1 = bp[1];
            float a[TM] = {a0.x, a0.y, a0.z, a0.w, a1.x, a1.y, a1.z, a1.w};
            float b[TN] = {b0.x, b0.y, b0.z, b0.w, b1.x, b1.y, b1.z, b1.w};
            #pragma unroll
            for (int i = 0; i < TM; i++)
                #pragma unroll
                for (int j = 0; j < TN; j++)
                    acc[i][j] = fmaf(a[i], b[j], acc[i][j]);
        }
    }

    // Epilogue: S = 2*acc - csum[col]
    float cs[TN];
    #pragma unroll
    for (int j = 0; j < TN; j++) {
        int col = n0 + tn * TN + j;
        cs[j] = (col < NCLS) ? g_csum[col] : 0.f;
    }
    #pragma unroll
    for (int i = 0; i < TM; i++) {
        int row = m0 + tm * TM + i;
        float* out = g_S + (size_t)row * NCLS;
        #pragma unroll
        for (int j = 0; j < TN; j++) {
            int col = n0 + tn * TN + j;
            if (col < NCLS)
                out[col] = 2.f * acc[i][j] - cs[j];
        }
    }
}

// ---------------------------------------------------------------------------
// Per-row reduction: one warp per row.
//   g_row[b] = lse(S_b) - (EPS/N) * sum_n S_bn - (1-EPS) * S[b, label_b]
// ---------------------------------------------------------------------------
__global__ void rowreduce_kernel(const int* __restrict__ l32) {
    const int warp = (blockIdx.x * blockDim.x + threadIdx.x) >> 5;
    const int lane = threadIdx.x & 31;
    if (warp >= B_ROWS) return;

    const float* s = g_S + (size_t)warp * NCLS;

    float v[32];
    float mx = -3.402823466e38f;
    #pragma unroll
    for (int j = 0; j < 32; j++) {
        int n = lane + 32 * j;
        v[j] = (n < NCLS) ? s[n] : -3.402823466e38f;
        mx = fmaxf(mx, v[j]);
    }
    #pragma unroll
    for (int off = 16; off > 0; off >>= 1)
        mx = fmaxf(mx, __shfl_xor_sync(0xFFFFFFFFu, mx, off));

    float se = 0.f, ss = 0.f;
    #pragma unroll
    for (int j = 0; j < 32; j++) {
        int n = lane + 32 * j;
        if (n < NCLS) {
            se += __expf(v[j] - mx);
            ss += v[j];
        }
    }
    #pragma unroll
    for (int off = 16; off > 0; off >>= 1) {
        se += __shfl_xor_sync(0xFFFFFFFFu, se, off);
        ss += __shfl_xor_sync(0xFFFFFFFFu, ss, off);
    }

    if (lane == 0) {
        int lab = g_labmode ? l32[warp] : l32[2 * warp];  // int32 vs int64(lo word)
        float slab = s[lab];
        float lse  = mx + logf(se);
        g_row[warp] = lse - (EPS / (float)NCLS) * ss - (1.0f - EPS) * slab;
    }
}

// ---------------------------------------------------------------------------
// Deterministic final mean: single block, fixed reduction order.
// ---------------------------------------------------------------------------
__global__ void finalize_kernel(float* __restrict__ out) {
    __shared__ float warp_sums[8];
    float s = 0.f;
    for (int i = threadIdx.x; i < B_ROWS; i += 256)
        s += g_row[i];
    #pragma unroll
    for (int off = 16; off > 0; off >>= 1)
        s += __shfl_xor_sync(0xFFFFFFFFu, s, off);
    if ((threadIdx.x & 31) == 0) warp_sums[threadIdx.x >> 5] = s;
    __syncthreads();
    if (threadIdx.x == 0) {
        float t = 0.f;
        #pragma unroll
        for (int w = 0; w < 8; w++) t += warp_sums[w];
        out[0] = t / (float)B_ROWS;
    }
}

// ---------------------------------------------------------------------------
extern "C" void kernel_launch(void* const* d_in, const int* in_sizes, int n_in,
                              void* d_out, int out_size) {
    const float* A   = (const float*)d_in[0];   // inputs [16384, 1000]
    const int*   lab = (const int*)d_in[1];     // labels (int32 or int64 — detected)
    const float* Cb  = (const float*)d_in[2];   // code_book [1000, 1000]
    float* out = (float*)d_out;

    detect_kernel<<<1, 256>>>(lab);
    csum_kernel<<<(NCLS * 32 + 255) / 256, 256>>>(Cb);
    dim3 grid((NCLS + BN - 1) / BN, B_ROWS / BM);
    gemm_kernel<<<grid, 256>>>(A, Cb);
    rowreduce_kernel<<<(B_ROWS * 32 + 255) / 256, 256>>>(lab);
    finalize_kernel<<<1, 256>>>(out);
}

// round 6
// speedup vs baseline: 3.1976x; 3.1976x over previous
#include <cuda_runtime.h>
#include <cuda_bf16.h>
#include <stdint.h>
#include <math.h>

#define B_ROWS 16384
#define NCLS   1000
#define KDIM   1000
#define EPS    0.1f

// GEMM config: bf16 hi/lo split (3 terms), K' = 3*1024
#define KP      3072
#define BM      128
#define BN      128
#define BK      64            // bf16 K per stage = 128 bytes/row
#define KITERS  (KP / BK)     // 48
#define NSTAGE  3
#define STAGE_BYTES 32768     // A 16KB + B 16KB
#define SMEM_TOTAL (NSTAGE * STAGE_BYTES)   // 96 KB

// Scratch (__device__ globals: allocation-free rule)
__device__ float          g_S[(size_t)B_ROWS * NCLS];
__device__ float          g_csum[NCLS];
__device__ float          g_row[B_ROWS];
__device__ int            g_labmode;
__device__ __nv_bfloat16  g_Ap[(size_t)B_ROWS * KP];   // [hi | hi | lo]
__device__ __nv_bfloat16  g_Cp[(size_t)1024  * KP];    // [hi | lo | hi], rows padded to 1024

// ---------------------------------------------------------------- PTX helpers
__device__ __forceinline__ uint32_t smem_u32(const void* p) {
    uint32_t a;
    asm("{ .reg .u64 t; cvta.to.shared.u64 t, %1; cvt.u32.u64 %0, t; }" : "=r"(a) : "l"(p));
    return a;
}
#define CP_ASYNC16(dst, src) \
    asm volatile("cp.async.cg.shared.global [%0], [%1], 16;\n" :: "r"(dst), "l"(src))
#define CP_COMMIT() asm volatile("cp.async.commit_group;\n" ::: "memory")
#define CP_WAIT1()  asm volatile("cp.async.wait_group 1;\n" ::: "memory")

__device__ __forceinline__ void ldmx4(uint32_t& r0, uint32_t& r1, uint32_t& r2,
                                      uint32_t& r3, uint32_t addr) {
    asm volatile("ldmatrix.sync.aligned.m8n8.x4.shared.b16 {%0,%1,%2,%3}, [%4];"
                 : "=r"(r0), "=r"(r1), "=r"(r2), "=r"(r3) : "r"(addr));
}
__device__ __forceinline__ void mma_bf16(float* c, const uint32_t* a, const uint32_t* b) {
    asm volatile("mma.sync.aligned.m16n8k16.row.col.f32.bf16.bf16.f32 "
                 "{%0,%1,%2,%3}, {%4,%5,%6,%7}, {%8,%9}, {%0,%1,%2,%3};"
                 : "+f"(c[0]), "+f"(c[1]), "+f"(c[2]), "+f"(c[3])
                 : "r"(a[0]), "r"(a[1]), "r"(a[2]), "r"(a[3]), "r"(b[0]), "r"(b[1]));
}

// ---------------------------------------------------------------- label dtype
__global__ void detect_kernel(const int* __restrict__ l32) {
    __shared__ int s_any;
    if (threadIdx.x == 0) s_any = 0;
    __syncthreads();
    int local = 0;
    for (int i = threadIdx.x; i < B_ROWS / 2; i += blockDim.x)
        local |= l32[2 * i + 1];
    if (local) atomicOr(&s_any, 1);
    __syncthreads();
    if (threadIdx.x == 0) g_labmode = (s_any != 0) ? 1 : 0;
}

// ---------------------------------------------------------------- csum
__global__ void csum_kernel(const float* __restrict__ Cb) {
    int warp = (blockIdx.x * blockDim.x + threadIdx.x) >> 5;
    int lane = threadIdx.x & 31;
    if (warp >= NCLS) return;
    const float* r = Cb + (size_t)warp * KDIM;
    float s = 0.f;
    for (int i = lane; i < KDIM; i += 32) s += r[i];
    #pragma unroll
    for (int off = 16; off > 0; off >>= 1)
        s += __shfl_xor_sync(0xFFFFFFFFu, s, off);
    if (lane == 0) g_csum[warp] = s;
}

// -------------------------------------------------- fp32 -> bf16 hi/lo splits
__global__ void convA_kernel(const float* __restrict__ A) {
    size_t t = (size_t)blockIdx.x * blockDim.x + threadIdx.x;  // 16384*128 threads
    int b = (int)(t >> 7);
    int k = (int)(t & 127) << 3;
    float v[8];
    if (k + 8 <= KDIM) {
        float4 x = *(const float4*)(A + (size_t)b * KDIM + k);
        float4 y = *(const float4*)(A + (size_t)b * KDIM + k + 4);
        v[0]=x.x; v[1]=x.y; v[2]=x.z; v[3]=x.w;
        v[4]=y.x; v[5]=y.y; v[6]=y.z; v[7]=y.w;
    } else {
        #pragma unroll
        for (int i = 0; i < 8; i++) {
            int kk = k + i;
            v[i] = (kk < KDIM) ? A[(size_t)b * KDIM + kk] : 0.f;
        }
    }
    union { __nv_bfloat16 h[8]; uint4 q; } uh, ul;
    #pragma unroll
    for (int i = 0; i < 8; i++) {
        uh.h[i] = __float2bfloat16(v[i]);
        ul.h[i] = __float2bfloat16(v[i] - __bfloat162float(uh.h[i]));
    }
    size_t base = (size_t)b * KP + k;
    *(uint4*)(g_Ap + base)        = uh.q;   // hi
    *(uint4*)(g_Ap + base + 1024) = uh.q;   // hi
    *(uint4*)(g_Ap + base + 2048) = ul.q;   // lo
}

__global__ void convC_kernel(const float* __restrict__ Cb) {
    size_t t = (size_t)blockIdx.x * blockDim.x + threadIdx.x;  // 1024*128 threads
    int n = (int)(t >> 7);
    int k = (int)(t & 127) << 3;
    float v[8];
    if (n < NCLS && k + 8 <= KDIM) {
        float4 x = *(const float4*)(Cb + (size_t)n * KDIM + k);
        float4 y = *(const float4*)(Cb + (size_t)n * KDIM + k + 4);
        v[0]=x.x; v[1]=x.y; v[2]=x.z; v[3]=x.w;
        v[4]=y.x; v[5]=y.y; v[6]=y.z; v[7]=y.w;
    } else {
        #pragma unroll
        for (int i = 0; i < 8; i++) {
            int kk = k + i;
            v[i] = (n < NCLS && kk < KDIM) ? Cb[(size_t)n * KDIM + kk] : 0.f;
        }
    }
    union { __nv_bfloat16 h[8]; uint4 q; } uh, ul;
    #pragma unroll
    for (int i = 0; i < 8; i++) {
        uh.h[i] = __float2bfloat16(v[i]);
        ul.h[i] = __float2bfloat16(v[i] - __bfloat162float(uh.h[i]));
    }
    size_t base = (size_t)n * KP + k;
    *(uint4*)(g_Cp + base)        = uh.q;   // hi   (pairs with A hi)
    *(uint4*)(g_Cp + base + 1024) = ul.q;   // lo   (pairs with A hi)
    *(uint4*)(g_Cp + base + 2048) = uh.q;   // hi   (pairs with A lo)
}

// ---------------------------------------------------------------- HMMA GEMM
// S[m0+128, n0+128] = 2 * (A' @ C'^T) - csum[n],  K' = 3072, bf16 mma.sync
__global__ void __launch_bounds__(256, 2)
gemm_kernel() {
    extern __shared__ char smem[];
    const uint32_t sb = smem_u32(smem);

    const int tid  = threadIdx.x;
    const int lane = tid & 31;
    const int wid  = tid >> 5;
    const int wm   = wid >> 1;        // 0..3  -> m offset wm*32
    const int wn   = wid & 1;         // 0..1  -> n offset wn*64
    const int m0   = blockIdx.y * BM;
    const int n0   = blockIdx.x * BN;

    // cp.async staging mapping: each thread owns 4 A-chunks + 4 B-chunks/stage
    const int srow = tid >> 3;        // 0..31 base row
    const int scol = tid & 7;         // chunk 0..7
    const uint32_t sdst = srow * 128 + ((scol ^ (srow & 7)) * 16);
    const __nv_bfloat16* Asrc = g_Ap + (size_t)(m0 + srow) * KP + scol * 8;
    const __nv_bfloat16* Bsrc = g_Cp + (size_t)(n0 + srow) * KP + scol * 8;

    auto load_stage = [&](int s, int st) {
        const int k0 = s * BK;
        const uint32_t sA = sb + st * STAGE_BYTES;
        const uint32_t sB = sA + 16384;
        #pragma unroll
        for (int i = 0; i < 4; i++) {   // rows srow + 32*i
            uint32_t d = sA + sdst + i * 32 * 128;
            CP_ASYNC16(d, Asrc + (size_t)(32 * i) * KP + k0);
        }
        #pragma unroll
        for (int i = 0; i < 4; i++) {
            uint32_t d = sB + sdst + i * 32 * 128;
            CP_ASYNC16(d, Bsrc + (size_t)(32 * i) * KP + k0);
        }
        CP_COMMIT();
    };

    float acc[2][8][4];
    #pragma unroll
    for (int mi = 0; mi < 2; mi++)
        #pragma unroll
        for (int ni = 0; ni < 8; ni++)
            #pragma unroll
            for (int j = 0; j < 4; j++) acc[mi][ni][j] = 0.f;

    // ldmatrix address components
    const int a_row = wm * 32 + (lane & 15);
    const int a_hi  = lane >> 4;              // chunk-half selector
    const int b_row = wn * 64 + (lane & 7) + ((lane >> 4) << 3);
    const int b_hi  = (lane >> 3) & 1;

    load_stage(0, 0);
    load_stage(1, 1);

    for (int s = 0; s < KITERS; s++) {
        const int st = s % NSTAGE;
        CP_WAIT1();
        __syncthreads();
        if (s + 2 < KITERS) load_stage(s + 2, (s + 2) % NSTAGE);

        const uint32_t sA = sb + st * STAGE_BYTES;
        const uint32_t sB = sA + 16384;

        #pragma unroll
        for (int kk = 0; kk < 4; kk++) {
            uint32_t af[2][4];
            #pragma unroll
            for (int mi = 0; mi < 2; mi++) {
                int row = a_row + mi * 16;
                uint32_t addr = sA + row * 128
                              + (((kk * 2 + a_hi) ^ (row & 7)) * 16);
                ldmx4(af[mi][0], af[mi][1], af[mi][2], af[mi][3], addr);
            }
            uint32_t bf[8][2];
            #pragma unroll
            for (int nt = 0; nt < 4; nt++) {
                int row = b_row + nt * 16;
                uint32_t addr = sB + row * 128
                              + (((kk * 2 + b_hi) ^ (row & 7)) * 16);
                uint32_t r0, r1, r2, r3;
                ldmx4(r0, r1, r2, r3, addr);
                bf[nt * 2][0]     = r0; bf[nt * 2][1]     = r1;
                bf[nt * 2 + 1][0] = r2; bf[nt * 2 + 1][1] = r3;
            }
            #pragma unroll
            for (int mi = 0; mi < 2; mi++)
                #pragma unroll
                for (int ni = 0; ni < 8; ni++)
                    mma_bf16(acc[mi][ni], af[mi], bf[ni]);
        }
    }

    // Epilogue: S = 2*acc - csum[col], float2 stores (col pairs stay in-bounds)
    const int r_base = m0 + wm * 32 + (lane >> 2);
    const int c_base = n0 + wn * 64 + (lane & 3) * 2;
    #pragma unroll
    for (int ni = 0; ni < 8; ni++) {
        int c = c_base + ni * 8;
        if (c < NCLS) {
            float cs0 = __ldg(&g_csum[c]);
            float cs1 = __ldg(&g_csum[c + 1]);
            #pragma unroll
            for (int mi = 0; mi < 2; mi++) {
                int row0 = r_base + mi * 16;
                float2 v0 = make_float2(2.f * acc[mi][ni][0] - cs0,
                                        2.f * acc[mi][ni][1] - cs1);
                float2 v1 = make_float2(2.f * acc[mi][ni][2] - cs0,
                                        2.f * acc[mi][ni][3] - cs1);
                *(float2*)(g_S + (size_t)row0 * NCLS + c)       = v0;
                *(float2*)(g_S + (size_t)(row0 + 8) * NCLS + c) = v1;
            }
        }
    }
}

// ---------------------------------------------------------------- rowreduce
__global__ void rowreduce_kernel(const int* __restrict__ l32) {
    const int warp = (blockIdx.x * blockDim.x + threadIdx.x) >> 5;
    const int lane = threadIdx.x & 31;
    if (warp >= B_ROWS) return;

    const float* s = g_S + (size_t)warp * NCLS;

    float v[32];
    float mx = -3.402823466e38f;
    #pragma unroll
    for (int j = 0; j < 32; j++) {
        int n = lane + 32 * j;
        v[j] = (n < NCLS) ? s[n] : -3.402823466e38f;
        mx = fmaxf(mx, v[j]);
    }
    #pragma unroll
    for (int off = 16; off > 0; off >>= 1)
        mx = fmaxf(mx, __shfl_xor_sync(0xFFFFFFFFu, mx, off));

    float se = 0.f, ss = 0.f;
    #pragma unroll
    for (int j = 0; j < 32; j++) {
        int n = lane + 32 * j;
        if (n < NCLS) {
            se += __expf(v[j] - mx);
            ss += v[j];
        }
    }
    #pragma unroll
    for (int off = 16; off > 0; off >>= 1) {
        se += __shfl_xor_sync(0xFFFFFFFFu, se, off);
        ss += __shfl_xor_sync(0xFFFFFFFFu, ss, off);
    }

    if (lane == 0) {
        int lab = g_labmode ? l32[warp] : l32[2 * warp];
        float slab = s[lab];
        float lse  = mx + logf(se);
        g_row[warp] = lse - (EPS / (float)NCLS) * ss - (1.0f - EPS) * slab;
    }
}

// ---------------------------------------------------------------- finalize
__global__ void finalize_kernel(float* __restrict__ out) {
    __shared__ float warp_sums[8];
    float s = 0.f;
    for (int i = threadIdx.x; i < B_ROWS; i += 256)
        s += g_row[i];
    #pragma unroll
    for (int off = 16; off > 0; off >>= 1)
        s += __shfl_xor_sync(0xFFFFFFFFu, s, off);
    if ((threadIdx.x & 31) == 0) warp_sums[threadIdx.x >> 5] = s;
    __syncthreads();
    if (threadIdx.x == 0) {
        float t = 0.f;
        #pragma unroll
        for (int w = 0; w < 8; w++) t += warp_sums[w];
        out[0] = t / (float)B_ROWS;
    }
}

// ----------------------------------------------------------------------------
extern "C" void kernel_launch(void* const* d_in, const int* in_sizes, int n_in,
                              void* d_out, int out_size) {
    const float* A   = (const float*)d_in[0];   // inputs [16384, 1000]
    const int*   lab = (const int*)d_in[1];     // labels (dtype auto-detected)
    const float* Cb  = (const float*)d_in[2];   // code_book [1000, 1000]
    float* out = (float*)d_out;

    cudaFuncSetAttribute(gemm_kernel,
                         cudaFuncAttributeMaxDynamicSharedMemorySize, SMEM_TOTAL);

    detect_kernel<<<1, 256>>>(lab);
    csum_kernel<<<(NCLS * 32 + 255) / 256, 256>>>(Cb);
    convA_kernel<<<B_ROWS * 128 / 256, 256>>>(A);
    convC_kernel<<<1024 * 128 / 256, 256>>>(Cb);
    gemm_kernel<<<dim3(1024 / BN, B_ROWS / BM), 256, SMEM_TOTAL>>>();
    rowreduce_kernel<<<(B_ROWS * 32 + 255) / 256, 256>>>(lab);
    finalize_kernel<<<1, 256>>>(out);
}

// round 7
// speedup vs baseline: 4.6987x; 1.4694x over previous
#include <cuda_runtime.h>
#include <cuda_bf16.h>
#include <stdint.h>
#include <math.h>

#define B_ROWS 16384
#define NCLS   1000
#define KDIM   1000
#define EPS    0.1f

// GEMM config: centered bf16 2-term split. A' = [Ah | Ah] (aliased), C' = [Ch | Cl]
#define KPA     1024          // physical K of A (hi only)
#define KPB     2048          // logical K' of the GEMM
#define BM      128
#define BN      128
#define BK      64            // bf16 K per stage = 128 bytes/row
#define KITERS  (KPB / BK)    // 32
#define NSTAGE  3
#define STAGE_BYTES 32768     // A 16KB + B 16KB
#define SMEM_TOTAL (NSTAGE * STAGE_BYTES)   // 96 KB

// Scratch (__device__ globals: allocation-free rule)
__device__ float          g_S[(size_t)B_ROWS * NCLS];
__device__ float          g_row[B_ROWS];
__device__ int            g_labmode;
__device__ __nv_bfloat16  g_Ah[(size_t)B_ROWS * KPA];  // bf16(a - 0.5)
__device__ __nv_bfloat16  g_Cp[(size_t)1024  * KPB];   // [Ch | Cl], rows padded to 1024

// ---------------------------------------------------------------- PTX helpers
__device__ __forceinline__ uint32_t smem_u32(const void* p) {
    uint32_t a;
    asm("{ .reg .u64 t; cvta.to.shared.u64 t, %1; cvt.u32.u64 %0, t; }" : "=r"(a) : "l"(p));
    return a;
}
#define CP_ASYNC16(dst, src) \
    asm volatile("cp.async.cg.shared.global [%0], [%1], 16;\n" :: "r"(dst), "l"(src))
#define CP_COMMIT() asm volatile("cp.async.commit_group;\n" ::: "memory")
#define CP_WAIT1()  asm volatile("cp.async.wait_group 1;\n" ::: "memory")

__device__ __forceinline__ void ldmx4(uint32_t& r0, uint32_t& r1, uint32_t& r2,
                                      uint32_t& r3, uint32_t addr) {
    asm volatile("ldmatrix.sync.aligned.m8n8.x4.shared.b16 {%0,%1,%2,%3}, [%4];"
                 : "=r"(r0), "=r"(r1), "=r"(r2), "=r"(r3) : "r"(addr));
}
__device__ __forceinline__ void mma_bf16(float* c, const uint32_t* a, const uint32_t* b) {
    asm volatile("mma.sync.aligned.m16n8k16.row.col.f32.bf16.bf16.f32 "
                 "{%0,%1,%2,%3}, {%4,%5,%6,%7}, {%8,%9}, {%0,%1,%2,%3};"
                 : "+f"(c[0]), "+f"(c[1]), "+f"(c[2]), "+f"(c[3])
                 : "r"(a[0]), "r"(a[1]), "r"(a[2]), "r"(a[3]), "r"(b[0]), "r"(b[1]));
}

// ---------------------------------------------------------------- label dtype
__global__ void detect_kernel(const int* __restrict__ l32) {
    __shared__ int s_any;
    if (threadIdx.x == 0) s_any = 0;
    __syncthreads();
    int local = 0;
    for (int i = threadIdx.x; i < B_ROWS / 2; i += blockDim.x)
        local |= l32[2 * i + 1];
    if (local) atomicOr(&s_any, 1);
    __syncthreads();
    if (threadIdx.x == 0) g_labmode = (s_any != 0) ? 1 : 0;
}

// -------------------------------------------------- centered bf16 conversions
__global__ void convA_kernel(const float* __restrict__ A) {
    size_t t = (size_t)blockIdx.x * blockDim.x + threadIdx.x;  // 16384*128 threads
    int b = (int)(t >> 7);
    int k = (int)(t & 127) << 3;
    float v[8];
    if (k + 8 <= KDIM) {
        float4 x = *(const float4*)(A + (size_t)b * KDIM + k);
        float4 y = *(const float4*)(A + (size_t)b * KDIM + k + 4);
        v[0]=x.x; v[1]=x.y; v[2]=x.z; v[3]=x.w;
        v[4]=y.x; v[5]=y.y; v[6]=y.z; v[7]=y.w;
        #pragma unroll
        for (int i = 0; i < 8; i++) v[i] -= 0.5f;
    } else {
        #pragma unroll
        for (int i = 0; i < 8; i++) {
            int kk = k + i;
            v[i] = (kk < KDIM) ? (A[(size_t)b * KDIM + kk] - 0.5f) : 0.f;
        }
    }
    union { __nv_bfloat16 h[8]; uint4 q; } uh;
    #pragma unroll
    for (int i = 0; i < 8; i++) uh.h[i] = __float2bfloat16(v[i]);
    *(uint4*)(g_Ah + (size_t)b * KPA + k) = uh.q;
}

__global__ void convC_kernel(const float* __restrict__ Cb) {
    size_t t = (size_t)blockIdx.x * blockDim.x + threadIdx.x;  // 1024*128 threads
    int n = (int)(t >> 7);
    int k = (int)(t & 127) << 3;
    float v[8];
    if (n < NCLS && k + 8 <= KDIM) {
        float4 x = *(const float4*)(Cb + (size_t)n * KDIM + k);
        float4 y = *(const float4*)(Cb + (size_t)n * KDIM + k + 4);
        v[0]=x.x; v[1]=x.y; v[2]=x.z; v[3]=x.w;
        v[4]=y.x; v[5]=y.y; v[6]=y.z; v[7]=y.w;
        #pragma unroll
        for (int i = 0; i < 8; i++) v[i] -= 0.5f;
    } else {
        #pragma unroll
        for (int i = 0; i < 8; i++) {
            int kk = k + i;
            v[i] = (n < NCLS && kk < KDIM) ? (Cb[(size_t)n * KDIM + kk] - 0.5f) : 0.f;
        }
    }
    union { __nv_bfloat16 h[8]; uint4 q; } uh, ul;
    #pragma unroll
    for (int i = 0; i < 8; i++) {
        uh.h[i] = __float2bfloat16(v[i]);
        ul.h[i] = __float2bfloat16(v[i] - __bfloat162float(uh.h[i]));
    }
    size_t base = (size_t)n * KPB + k;
    *(uint4*)(g_Cp + base)        = uh.q;   // Ch
    *(uint4*)(g_Cp + base + 1024) = ul.q;   // Cl
}

// ---------------------------------------------------------------- HMMA GEMM
// S[m0+128, n0+128] = 2 * (A' @ C'^T),  K' = 2048, A K-halves alias g_Ah
__global__ void __launch_bounds__(256, 2)
gemm_kernel() {
    extern __shared__ char smem[];
    const uint32_t sb = smem_u32(smem);

    const int tid  = threadIdx.x;
    const int lane = tid & 31;
    const int wid  = tid >> 5;
    const int wm   = wid >> 1;        // 0..3  -> m offset wm*32
    const int wn   = wid & 1;         // 0..1  -> n offset wn*64
    const int m0   = blockIdx.y * BM;
    const int n0   = blockIdx.x * BN;

    // cp.async staging mapping: each thread owns 4 A-chunks + 4 B-chunks/stage
    const int srow = tid >> 3;        // 0..31 base row
    const int scol = tid & 7;         // chunk 0..7
    const uint32_t sdst = srow * 128 + ((scol ^ (srow & 7)) * 16);
    const __nv_bfloat16* Asrc = g_Ah + (size_t)(m0 + srow) * KPA + scol * 8;
    const __nv_bfloat16* Bsrc = g_Cp + (size_t)(n0 + srow) * KPB + scol * 8;

    auto load_stage = [&](int s, int st) {
        const int k0  = s * BK;
        const int k0a = k0 & (KPA - 1);      // A aliases its hi data in both halves
        const uint32_t sA = sb + st * STAGE_BYTES;
        const uint32_t sB = sA + 16384;
        #pragma unroll
        for (int i = 0; i < 4; i++) {
            uint32_t d = sA + sdst + i * 32 * 128;
            CP_ASYNC16(d, Asrc + (size_t)(32 * i) * KPA + k0a);
        }
        #pragma unroll
        for (int i = 0; i < 4; i++) {
            uint32_t d = sB + sdst + i * 32 * 128;
            CP_ASYNC16(d, Bsrc + (size_t)(32 * i) * KPB + k0);
        }
        CP_COMMIT();
    };

    float acc[2][8][4];
    #pragma unroll
    for (int mi = 0; mi < 2; mi++)
        #pragma unroll
        for (int ni = 0; ni < 8; ni++)
            #pragma unroll
            for (int j = 0; j < 4; j++) acc[mi][ni][j] = 0.f;

    const int a_row = wm * 32 + (lane & 15);
    const int a_hi  = lane >> 4;
    const int b_row = wn * 64 + (lane & 7) + ((lane >> 4) << 3);
    const int b_hi  = (lane >> 3) & 1;

    load_stage(0, 0);
    load_stage(1, 1);

    for (int s = 0; s < KITERS; s++) {
        const int st = s % NSTAGE;
        CP_WAIT1();
        __syncthreads();
        if (s + 2 < KITERS) load_stage(s + 2, (s + 2) % NSTAGE);

        const uint32_t sA = sb + st * STAGE_BYTES;
        const uint32_t sB = sA + 16384;

        #pragma unroll
        for (int kk = 0; kk < 4; kk++) {
            uint32_t af[2][4];
            #pragma unroll
            for (int mi = 0; mi < 2; mi++) {
                int row = a_row + mi * 16;
                uint32_t addr = sA + row * 128
                              + (((kk * 2 + a_hi) ^ (row & 7)) * 16);
                ldmx4(af[mi][0], af[mi][1], af[mi][2], af[mi][3], addr);
            }
            uint32_t bf[8][2];
            #pragma unroll
            for (int nt = 0; nt < 4; nt++) {
                int row = b_row + nt * 16;
                uint32_t addr = sB + row * 128
                              + (((kk * 2 + b_hi) ^ (row & 7)) * 16);
                uint32_t r0, r1, r2, r3;
                ldmx4(r0, r1, r2, r3, addr);
                bf[nt * 2][0]     = r0; bf[nt * 2][1]     = r1;
                bf[nt * 2 + 1][0] = r2; bf[nt * 2 + 1][1] = r3;
            }
            #pragma unroll
            for (int mi = 0; mi < 2; mi++)
                #pragma unroll
                for (int ni = 0; ni < 8; ni++)
                    mma_bf16(acc[mi][ni], af[mi], bf[ni]);
        }
    }

    // Epilogue: S = 2*acc (csum cancelled by centering; row consts cancel in loss)
    const int r_base = m0 + wm * 32 + (lane >> 2);
    const int c_base = n0 + wn * 64 + (lane & 3) * 2;
    #pragma unroll
    for (int ni = 0; ni < 8; ni++) {
        int c = c_base + ni * 8;
        if (c < NCLS) {
            #pragma unroll
            for (int mi = 0; mi < 2; mi++) {
                int row0 = r_base + mi * 16;
                float2 v0 = make_float2(2.f * acc[mi][ni][0], 2.f * acc[mi][ni][1]);
                float2 v1 = make_float2(2.f * acc[mi][ni][2], 2.f * acc[mi][ni][3]);
                *(float2*)(g_S + (size_t)row0 * NCLS + c)       = v0;
                *(float2*)(g_S + (size_t)(row0 + 8) * NCLS + c) = v1;
            }
        }
    }
}

// ---------------------------------------------------------------- rowreduce
__global__ void rowreduce_kernel(const int* __restrict__ l32) {
    const int warp = (blockIdx.x * blockDim.x + threadIdx.x) >> 5;
    const int lane = threadIdx.x & 31;
    if (warp >= B_ROWS) return;

    const float* s = g_S + (size_t)warp * NCLS;

    float v[32];
    float mx = -3.402823466e38f;
    #pragma unroll
    for (int j = 0; j < 32; j++) {
        int n = lane + 32 * j;
        v[j] = (n < NCLS) ? s[n] : -3.402823466e38f;
        mx = fmaxf(mx, v[j]);
    }
    #pragma unroll
    for (int off = 16; off > 0; off >>= 1)
        mx = fmaxf(mx, __shfl_xor_sync(0xFFFFFFFFu, mx, off));

    float se = 0.f, ss = 0.f;
    #pragma unroll
    for (int j = 0; j < 32; j++) {
        int n = lane + 32 * j;
        if (n < NCLS) {
            se += __expf(v[j] - mx);
            ss += v[j];
        }
    }
    #pragma unroll
    for (int off = 16; off > 0; off >>= 1) {
        se += __shfl_xor_sync(0xFFFFFFFFu, se, off);
        ss += __shfl_xor_sync(0xFFFFFFFFu, ss, off);
    }

    if (lane == 0) {
        int lab = g_labmode ? l32[warp] : l32[2 * warp];
        float slab = s[lab];
        float lse  = mx + logf(se);
        g_row[warp] = lse - (EPS / (float)NCLS) * ss - (1.0f - EPS) * slab;
    }
}

// ---------------------------------------------------------------- finalize
__global__ void finalize_kernel(float* __restrict__ out) {
    __shared__ float warp_sums[8];
    float s = 0.f;
    for (int i = threadIdx.x; i < B_ROWS; i += 256)
        s += g_row[i];
    #pragma unroll
    for (int off = 16; off > 0; off >>= 1)
        s += __shfl_xor_sync(0xFFFFFFFFu, s, off);
    if ((threadIdx.x & 31) == 0) warp_sums[threadIdx.x >> 5] = s;
    __syncthreads();
    if (threadIdx.x == 0) {
        float t = 0.f;
        #pragma unroll
        for (int w = 0; w < 8; w++) t += warp_sums[w];
        out[0] = t / (float)B_ROWS;
    }
}

// ----------------------------------------------------------------------------
extern "C" void kernel_launch(void* const* d_in, const int* in_sizes, int n_in,
                              void* d_out, int out_size) {
    const float* A   = (const float*)d_in[0];   // inputs [16384, 1000]
    const int*   lab = (const int*)d_in[1];     // labels (dtype auto-detected)
    const float* Cb  = (const float*)d_in[2];   // code_book [1000, 1000]
    float* out = (float*)d_out;

    cudaFuncSetAttribute(gemm_kernel,
                         cudaFuncAttributeMaxDynamicSharedMemorySize, SMEM_TOTAL);

    detect_kernel<<<1, 256>>>(lab);
    convA_kernel<<<B_ROWS * 128 / 256, 256>>>(A);
    convC_kernel<<<1024 * 128 / 256, 256>>>(Cb);
    gemm_kernel<<<dim3(1024 / BN, B_ROWS / BM), 256, SMEM_TOTAL>>>();
    rowreduce_kernel<<<(B_ROWS * 32 + 255) / 256, 256>>>(lab);
    finalize_kernel<<<1, 256>>>(out);
}

// round 8
// speedup vs baseline: 7.0292x; 1.4960x over previous
#include <cuda_runtime.h>
#include <cuda_fp16.h>
#include <stdint.h>
#include <math.h>

#define B_ROWS 16384
#define NCLS   1000
#define KDIM   1000
#define EPS    0.1f

// GEMM config: centered fp16 single-term, K = 1024
#define KPA     1024
#define BM      128
#define BN      128
#define BK      64            // fp16 K per stage = 128 bytes/row
#define KITERS  (KPA / BK)    // 16
#define NSTAGE  3
#define STAGE_BYTES 32768     // A 16KB + B 16KB
#define SMEM_TOTAL (NSTAGE * STAGE_BYTES)   // 96 KB

// Scratch (__device__ globals: allocation-free rule)
__device__ float   g_S[(size_t)B_ROWS * NCLS];
__device__ float   g_row[B_ROWS];
__device__ int     g_labmode;
__device__ __half  g_Ah[(size_t)B_ROWS * KPA];  // fp16(a - 0.5)
__device__ __half  g_Ch[(size_t)1024  * KPA];   // fp16(c - 0.5), rows padded to 1024

// ---------------------------------------------------------------- PTX helpers
__device__ __forceinline__ uint32_t smem_u32(const void* p) {
    uint32_t a;
    asm("{ .reg .u64 t; cvta.to.shared.u64 t, %1; cvt.u32.u64 %0, t; }" : "=r"(a) : "l"(p));
    return a;
}
#define CP_ASYNC16(dst, src) \
    asm volatile("cp.async.cg.shared.global [%0], [%1], 16;\n" :: "r"(dst), "l"(src))
#define CP_COMMIT() asm volatile("cp.async.commit_group;\n" ::: "memory")
#define CP_WAIT1()  asm volatile("cp.async.wait_group 1;\n" ::: "memory")

__device__ __forceinline__ void ldmx4(uint32_t& r0, uint32_t& r1, uint32_t& r2,
                                      uint32_t& r3, uint32_t addr) {
    asm volatile("ldmatrix.sync.aligned.m8n8.x4.shared.b16 {%0,%1,%2,%3}, [%4];"
                 : "=r"(r0), "=r"(r1), "=r"(r2), "=r"(r3) : "r"(addr));
}
__device__ __forceinline__ void mma_fp16(float* c, const uint32_t* a, const uint32_t* b) {
    asm volatile("mma.sync.aligned.m16n8k16.row.col.f32.f16.f16.f32 "
                 "{%0,%1,%2,%3}, {%4,%5,%6,%7}, {%8,%9}, {%0,%1,%2,%3};"
                 : "+f"(c[0]), "+f"(c[1]), "+f"(c[2]), "+f"(c[3])
                 : "r"(a[0]), "r"(a[1]), "r"(a[2]), "r"(a[3]), "r"(b[0]), "r"(b[1]));
}

// ---------------------------------------------------------------- label dtype
__global__ void detect_kernel(const int* __restrict__ l32) {
    __shared__ int s_any;
    if (threadIdx.x == 0) s_any = 0;
    __syncthreads();
    int local = 0;
    for (int i = threadIdx.x; i < B_ROWS / 2; i += blockDim.x)
        local |= l32[2 * i + 1];
    if (local) atomicOr(&s_any, 1);
    __syncthreads();
    if (threadIdx.x == 0) g_labmode = (s_any != 0) ? 1 : 0;
}

// -------------------------------------------------- centered fp16 conversions
__global__ void convA_kernel(const float* __restrict__ A) {
    size_t t = (size_t)blockIdx.x * blockDim.x + threadIdx.x;  // 16384*128 threads
    int b = (int)(t >> 7);
    int k = (int)(t & 127) << 3;
    float v[8];
    if (k + 8 <= KDIM) {
        float4 x = *(const float4*)(A + (size_t)b * KDIM + k);
        float4 y = *(const float4*)(A + (size_t)b * KDIM + k + 4);
        v[0]=x.x; v[1]=x.y; v[2]=x.z; v[3]=x.w;
        v[4]=y.x; v[5]=y.y; v[6]=y.z; v[7]=y.w;
        #pragma unroll
        for (int i = 0; i < 8; i++) v[i] -= 0.5f;
    } else {
        #pragma unroll
        for (int i = 0; i < 8; i++) {
            int kk = k + i;
            v[i] = (kk < KDIM) ? (A[(size_t)b * KDIM + kk] - 0.5f) : 0.f;
        }
    }
    union { __half h[8]; uint4 q; } uh;
    #pragma unroll
    for (int i = 0; i < 8; i++) uh.h[i] = __float2half_rn(v[i]);
    *(uint4*)(g_Ah + (size_t)b * KPA + k) = uh.q;
}

__global__ void convC_kernel(const float* __restrict__ Cb) {
    size_t t = (size_t)blockIdx.x * blockDim.x + threadIdx.x;  // 1024*128 threads
    int n = (int)(t >> 7);
    int k = (int)(t & 127) << 3;
    float v[8];
    if (n < NCLS && k + 8 <= KDIM) {
        float4 x = *(const float4*)(Cb + (size_t)n * KDIM + k);
        float4 y = *(const float4*)(Cb + (size_t)n * KDIM + k + 4);
        v[0]=x.x; v[1]=x.y; v[2]=x.z; v[3]=x.w;
        v[4]=y.x; v[5]=y.y; v[6]=y.z; v[7]=y.w;
        #pragma unroll
        for (int i = 0; i < 8; i++) v[i] -= 0.5f;
    } else {
        #pragma unroll
        for (int i = 0; i < 8; i++) {
            int kk = k + i;
            v[i] = (n < NCLS && kk < KDIM) ? (Cb[(size_t)n * KDIM + kk] - 0.5f) : 0.f;
        }
    }
    union { __half h[8]; uint4 q; } uh;
    #pragma unroll
    for (int i = 0; i < 8; i++) uh.h[i] = __float2half_rn(v[i]);
    *(uint4*)(g_Ch + (size_t)n * KPA + k) = uh.q;
}

// ---------------------------------------------------------------- HMMA GEMM
// S[m0+128, n0+128] = 2 * (A' @ C'^T),  K = 1024, fp16 mma.sync
__global__ void __launch_bounds__(256, 2)
gemm_kernel() {
    extern __shared__ char smem[];
    const uint32_t sb = smem_u32(smem);

    const int tid  = threadIdx.x;
    const int lane = tid & 31;
    const int wid  = tid >> 5;
    const int wm   = wid >> 1;        // 0..3  -> m offset wm*32
    const int wn   = wid & 1;         // 0..1  -> n offset wn*64
    const int m0   = blockIdx.y * BM;
    const int n0   = blockIdx.x * BN;

    // cp.async staging mapping: each thread owns 4 A-chunks + 4 B-chunks/stage
    const int srow = tid >> 3;        // 0..31 base row
    const int scol = tid & 7;         // chunk 0..7
    const uint32_t sdst = srow * 128 + ((scol ^ (srow & 7)) * 16);
    const __half* Asrc = g_Ah + (size_t)(m0 + srow) * KPA + scol * 8;
    const __half* Bsrc = g_Ch + (size_t)(n0 + srow) * KPA + scol * 8;

    auto load_stage = [&](int s, int st) {
        const int k0 = s * BK;
        const uint32_t sA = sb + st * STAGE_BYTES;
        const uint32_t sB = sA + 16384;
        #pragma unroll
        for (int i = 0; i < 4; i++) {
            uint32_t d = sA + sdst + i * 32 * 128;
            CP_ASYNC16(d, Asrc + (size_t)(32 * i) * KPA + k0);
        }
        #pragma unroll
        for (int i = 0; i < 4; i++) {
            uint32_t d = sB + sdst + i * 32 * 128;
            CP_ASYNC16(d, Bsrc + (size_t)(32 * i) * KPA + k0);
        }
        CP_COMMIT();
    };

    float acc[2][8][4];
    #pragma unroll
    for (int mi = 0; mi < 2; mi++)
        #pragma unroll
        for (int ni = 0; ni < 8; ni++)
            #pragma unroll
            for (int j = 0; j < 4; j++) acc[mi][ni][j] = 0.f;

    const int a_row = wm * 32 + (lane & 15);
    const int a_hi  = lane >> 4;
    const int b_row = wn * 64 + (lane & 7) + ((lane >> 4) << 3);
    const int b_hi  = (lane >> 3) & 1;

    load_stage(0, 0);
    load_stage(1, 1);

    for (int s = 0; s < KITERS; s++) {
        const int st = s % NSTAGE;
        CP_WAIT1();
        __syncthreads();
        if (s + 2 < KITERS) load_stage(s + 2, (s + 2) % NSTAGE);

        const uint32_t sA = sb + st * STAGE_BYTES;
        const uint32_t sB = sA + 16384;

        #pragma unroll
        for (int kk = 0; kk < 4; kk++) {
            uint32_t af[2][4];
            #pragma unroll
            for (int mi = 0; mi < 2; mi++) {
                int row = a_row + mi * 16;
                uint32_t addr = sA + row * 128
                              + (((kk * 2 + a_hi) ^ (row & 7)) * 16);
                ldmx4(af[mi][0], af[mi][1], af[mi][2], af[mi][3], addr);
            }
            uint32_t bf[8][2];
            #pragma unroll
            for (int nt = 0; nt < 4; nt++) {
                int row = b_row + nt * 16;
                uint32_t addr = sB + row * 128
                              + (((kk * 2 + b_hi) ^ (row & 7)) * 16);
                uint32_t r0, r1, r2, r3;
                ldmx4(r0, r1, r2, r3, addr);
                bf[nt * 2][0]     = r0; bf[nt * 2][1]     = r1;
                bf[nt * 2 + 1][0] = r2; bf[nt * 2 + 1][1] = r3;
            }
            #pragma unroll
            for (int mi = 0; mi < 2; mi++)
                #pragma unroll
                for (int ni = 0; ni < 8; ni++)
                    mma_fp16(acc[mi][ni], af[mi], bf[ni]);
        }
    }

    // Epilogue: S = 2*acc (csum cancelled by centering; row consts cancel in loss)
    const int r_base = m0 + wm * 32 + (lane >> 2);
    const int c_base = n0 + wn * 64 + (lane & 3) * 2;
    #pragma unroll
    for (int ni = 0; ni < 8; ni++) {
        int c = c_base + ni * 8;
        if (c < NCLS) {
            #pragma unroll
            for (int mi = 0; mi < 2; mi++) {
                int row0 = r_base + mi * 16;
                float2 v0 = make_float2(2.f * acc[mi][ni][0], 2.f * acc[mi][ni][1]);
                float2 v1 = make_float2(2.f * acc[mi][ni][2], 2.f * acc[mi][ni][3]);
                *(float2*)(g_S + (size_t)row0 * NCLS + c)       = v0;
                *(float2*)(g_S + (size_t)(row0 + 8) * NCLS + c) = v1;
            }
        }
    }
}

// ---------------------------------------------------------------- rowreduce
__global__ void rowreduce_kernel(const int* __restrict__ l32) {
    const int warp = (blockIdx.x * blockDim.x + threadIdx.x) >> 5;
    const int lane = threadIdx.x & 31;
    if (warp >= B_ROWS) return;

    const float* s = g_S + (size_t)warp * NCLS;

    float v[32];
    float mx = -3.402823466e38f;
    #pragma unroll
    for (int j = 0; j < 32; j++) {
        int n = lane + 32 * j;
        v[j] = (n < NCLS) ? s[n] : -3.402823466e38f;
        mx = fmaxf(mx, v[j]);
    }
    #pragma unroll
    for (int off = 16; off > 0; off >>= 1)
        mx = fmaxf(mx, __shfl_xor_sync(0xFFFFFFFFu, mx, off));

    float se = 0.f, ss = 0.f;
    #pragma unroll
    for (int j = 0; j < 32; j++) {
        int n = lane + 32 * j;
        if (n < NCLS) {
            se += __expf(v[j] - mx);
            ss += v[j];
        }
    }
    #pragma unroll
    for (int off = 16; off > 0; off >>= 1) {
        se += __shfl_xor_sync(0xFFFFFFFFu, se, off);
        ss += __shfl_xor_sync(0xFFFFFFFFu, ss, off);
    }

    if (lane == 0) {
        int lab = g_labmode ? l32[warp] : l32[2 * warp];
        float slab = s[lab];
        float lse  = mx + logf(se);
        g_row[warp] = lse - (EPS / (float)NCLS) * ss - (1.0f - EPS) * slab;
    }
}

// ---------------------------------------------------------------- finalize
__global__ void finalize_kernel(float* __restrict__ out) {
    __shared__ float warp_sums[8];
    float s = 0.f;
    for (int i = threadIdx.x; i < B_ROWS; i += 256)
        s += g_row[i];
    #pragma unroll
    for (int off = 16; off > 0; off >>= 1)
        s += __shfl_xor_sync(0xFFFFFFFFu, s, off);
    if ((threadIdx.x & 31) == 0) warp_sums[threadIdx.x >> 5] = s;
    __syncthreads();
    if (threadIdx.x == 0) {
        float t = 0.f;
        #pragma unroll
        for (int w = 0; w < 8; w++) t += warp_sums[w];
        out[0] = t / (float)B_ROWS;
    }
}

// ----------------------------------------------------------------------------
extern "C" void kernel_launch(void* const* d_in, const int* in_sizes, int n_in,
                              void* d_out, int out_size) {
    const float* A   = (const float*)d_in[0];   // inputs [16384, 1000]
    const int*   lab = (const int*)d_in[1];     // labels (dtype auto-detected)
    const float* Cb  = (const float*)d_in[2];   // code_book [1000, 1000]
    float* out = (float*)d_out;

    cudaFuncSetAttribute(gemm_kernel,
                         cudaFuncAttributeMaxDynamicSharedMemorySize, SMEM_TOTAL);

    detect_kernel<<<1, 256>>>(lab);
    convA_kernel<<<B_ROWS * 128 / 256, 256>>>(A);
    convC_kernel<<<1024 * 128 / 256, 256>>>(Cb);
    gemm_kernel<<<dim3(1024 / BN, B_ROWS / BM), 256, SMEM_TOTAL>>>();
    rowreduce_kernel<<<(B_ROWS * 32 + 255) / 256, 256>>>(lab);
    finalize_kernel<<<1, 256>>>(out);
}

// round 9
// speedup vs baseline: 8.3037x; 1.1813x over previous
#include <cuda_runtime.h>
#include <cuda_fp16.h>
#include <stdint.h>
#include <math.h>
#include <float.h>

#define B_ROWS 16384
#define NCLS   1000
#define KDIM   1000
#define EPS    0.1f

// GEMM config: centered fp16 single-term, K = 1024
#define KPA     1024
#define BM      128
#define BN      128
#define BK      64            // fp16 K per stage = 128 bytes/row
#define KITERS  (KPA / BK)    // 16
#define NSTAGE  3
#define STAGE_BYTES 32768     // A 16KB + B 16KB
#define SMEM_TOTAL (NSTAGE * STAGE_BYTES)   // 96 KB
#define NTILES  16            // 16 x 64-col softmax partial tiles

// Scratch (__device__ globals: allocation-free rule)
__device__ float4  g_part[NTILES][B_ROWS];   // {max, sumexp, sum, S[label]}
__device__ float   g_row[B_ROWS];
__device__ int     g_labmode;
__device__ __half  g_Ah[(size_t)B_ROWS * KPA];  // fp16(a - 0.5)
__device__ __half  g_Ch[(size_t)1024  * KPA];   // fp16(c - 0.5), rows padded to 1024

// ---------------------------------------------------------------- PTX helpers
__device__ __forceinline__ uint32_t smem_u32(const void* p) {
    uint32_t a;
    asm("{ .reg .u64 t; cvta.to.shared.u64 t, %1; cvt.u32.u64 %0, t; }" : "=r"(a) : "l"(p));
    return a;
}
#define CP_ASYNC16(dst, src) \
    asm volatile("cp.async.cg.shared.global [%0], [%1], 16;\n" :: "r"(dst), "l"(src))
#define CP_COMMIT() asm volatile("cp.async.commit_group;\n" ::: "memory")
#define CP_WAIT1()  asm volatile("cp.async.wait_group 1;\n" ::: "memory")

__device__ __forceinline__ void ldmx4(uint32_t& r0, uint32_t& r1, uint32_t& r2,
                                      uint32_t& r3, uint32_t addr) {
    asm volatile("ldmatrix.sync.aligned.m8n8.x4.shared.b16 {%0,%1,%2,%3}, [%4];"
                 : "=r"(r0), "=r"(r1), "=r"(r2), "=r"(r3) : "r"(addr));
}
__device__ __forceinline__ void mma_fp16(float* c, const uint32_t* a, const uint32_t* b) {
    asm volatile("mma.sync.aligned.m16n8k16.row.col.f32.f16.f16.f32 "
                 "{%0,%1,%2,%3}, {%4,%5,%6,%7}, {%8,%9}, {%0,%1,%2,%3};"
                 : "+f"(c[0]), "+f"(c[1]), "+f"(c[2]), "+f"(c[3])
                 : "r"(a[0]), "r"(a[1]), "r"(a[2]), "r"(a[3]), "r"(b[0]), "r"(b[1]));
}

// ---------------------------------------------------------------- label dtype
__global__ void detect_kernel(const int* __restrict__ l32) {
    __shared__ int s_any;
    if (threadIdx.x == 0) s_any = 0;
    __syncthreads();
    int local = 0;
    for (int i = threadIdx.x; i < B_ROWS / 2; i += blockDim.x)
        local |= l32[2 * i + 1];
    if (local) atomicOr(&s_any, 1);
    __syncthreads();
    if (threadIdx.x == 0) g_labmode = (s_any != 0) ? 1 : 0;
}

// -------------------------------------------------- centered fp16 conversions
__global__ void convA_kernel(const float* __restrict__ A) {
    size_t t = (size_t)blockIdx.x * blockDim.x + threadIdx.x;  // 16384*128 threads
    int b = (int)(t >> 7);
    int k = (int)(t & 127) << 3;
    float v[8];
    if (k + 8 <= KDIM) {
        float4 x = *(const float4*)(A + (size_t)b * KDIM + k);
        float4 y = *(const float4*)(A + (size_t)b * KDIM + k + 4);
        v[0]=x.x; v[1]=x.y; v[2]=x.z; v[3]=x.w;
        v[4]=y.x; v[5]=y.y; v[6]=y.z; v[7]=y.w;
        #pragma unroll
        for (int i = 0; i < 8; i++) v[i] -= 0.5f;
    } else {
        #pragma unroll
        for (int i = 0; i < 8; i++) {
            int kk = k + i;
            v[i] = (kk < KDIM) ? (A[(size_t)b * KDIM + kk] - 0.5f) : 0.f;
        }
    }
    union { __half h[8]; uint4 q; } uh;
    #pragma unroll
    for (int i = 0; i < 8; i++) uh.h[i] = __float2half_rn(v[i]);
    *(uint4*)(g_Ah + (size_t)b * KPA + k) = uh.q;
}

__global__ void convC_kernel(const float* __restrict__ Cb) {
    size_t t = (size_t)blockIdx.x * blockDim.x + threadIdx.x;  // 1024*128 threads
    int n = (int)(t >> 7);
    int k = (int)(t & 127) << 3;
    float v[8];
    if (n < NCLS && k + 8 <= KDIM) {
        float4 x = *(const float4*)(Cb + (size_t)n * KDIM + k);
        float4 y = *(const float4*)(Cb + (size_t)n * KDIM + k + 4);
        v[0]=x.x; v[1]=x.y; v[2]=x.z; v[3]=x.w;
        v[4]=y.x; v[5]=y.y; v[6]=y.z; v[7]=y.w;
        #pragma unroll
        for (int i = 0; i < 8; i++) v[i] -= 0.5f;
    } else {
        #pragma unroll
        for (int i = 0; i < 8; i++) {
            int kk = k + i;
            v[i] = (n < NCLS && kk < KDIM) ? (Cb[(size_t)n * KDIM + kk] - 0.5f) : 0.f;
        }
    }
    union { __half h[8]; uint4 q; } uh;
    #pragma unroll
    for (int i = 0; i < 8; i++) uh.h[i] = __float2half_rn(v[i]);
    *(uint4*)(g_Ch + (size_t)n * KPA + k) = uh.q;
}

// ---------------------------------------------------------------- HMMA GEMM
// Computes S = 2 * (A' @ C'^T) and fused softmax partials per 64-col tile.
__global__ void __launch_bounds__(256, 2)
gemm_kernel(const int* __restrict__ l32) {
    extern __shared__ char smem[];
    const uint32_t sb = smem_u32(smem);

    const int tid  = threadIdx.x;
    const int lane = tid & 31;
    const int wid  = tid >> 5;
    const int wm   = wid >> 1;        // 0..3  -> m offset wm*32
    const int wn   = wid & 1;         // 0..1  -> n offset wn*64
    const int m0   = blockIdx.y * BM;
    const int n0   = blockIdx.x * BN;

    // cp.async staging mapping: each thread owns 4 A-chunks + 4 B-chunks/stage
    const int srow = tid >> 3;        // 0..31 base row
    const int scol = tid & 7;         // chunk 0..7
    const uint32_t sdst = srow * 128 + ((scol ^ (srow & 7)) * 16);
    const __half* Asrc = g_Ah + (size_t)(m0 + srow) * KPA + scol * 8;
    const __half* Bsrc = g_Ch + (size_t)(n0 + srow) * KPA + scol * 8;

    auto load_stage = [&](int s, int st) {
        const int k0 = s * BK;
        const uint32_t sA = sb + st * STAGE_BYTES;
        const uint32_t sB = sA + 16384;
        #pragma unroll
        for (int i = 0; i < 4; i++) {
            uint32_t d = sA + sdst + i * 32 * 128;
            CP_ASYNC16(d, Asrc + (size_t)(32 * i) * KPA + k0);
        }
        #pragma unroll
        for (int i = 0; i < 4; i++) {
            uint32_t d = sB + sdst + i * 32 * 128;
            CP_ASYNC16(d, Bsrc + (size_t)(32 * i) * KPA + k0);
        }
        CP_COMMIT();
    };

    float acc[2][8][4];
    #pragma unroll
    for (int mi = 0; mi < 2; mi++)
        #pragma unroll
        for (int ni = 0; ni < 8; ni++)
            #pragma unroll
            for (int j = 0; j < 4; j++) acc[mi][ni][j] = 0.f;

    const int a_row = wm * 32 + (lane & 15);
    const int a_hi  = lane >> 4;
    const int b_row = wn * 64 + (lane & 7) + ((lane >> 4) << 3);
    const int b_hi  = (lane >> 3) & 1;

    load_stage(0, 0);
    load_stage(1, 1);

    for (int s = 0; s < KITERS; s++) {
        const int st = s % NSTAGE;
        CP_WAIT1();
        __syncthreads();
        if (s + 2 < KITERS) load_stage(s + 2, (s + 2) % NSTAGE);

        const uint32_t sA = sb + st * STAGE_BYTES;
        const uint32_t sB = sA + 16384;

        #pragma unroll
        for (int kk = 0; kk < 4; kk++) {
            uint32_t af[2][4];
            #pragma unroll
            for (int mi = 0; mi < 2; mi++) {
                int row = a_row + mi * 16;
                uint32_t addr = sA + row * 128
                              + (((kk * 2 + a_hi) ^ (row & 7)) * 16);
                ldmx4(af[mi][0], af[mi][1], af[mi][2], af[mi][3], addr);
            }
            uint32_t bf[8][2];
            #pragma unroll
            for (int nt = 0; nt < 4; nt++) {
                int row = b_row + nt * 16;
                uint32_t addr = sB + row * 128
                              + (((kk * 2 + b_hi) ^ (row & 7)) * 16);
                uint32_t r0, r1, r2, r3;
                ldmx4(r0, r1, r2, r3, addr);
                bf[nt * 2][0]     = r0; bf[nt * 2][1]     = r1;
                bf[nt * 2 + 1][0] = r2; bf[nt * 2 + 1][1] = r3;
            }
            #pragma unroll
            for (int mi = 0; mi < 2; mi++)
                #pragma unroll
                for (int ni = 0; ni < 8; ni++)
                    mma_fp16(acc[mi][ni], af[mi], bf[ni]);
        }
    }

    // ---------------- fused softmax-partial epilogue -----------------------
    // Quad lanes {q*4..q*4+3} own the same rows; each thread holds 16 cols/row.
    const int quad  = lane >> 2;
    const int nwarp = n0 + wn * 64;                   // this warp's 64-col tile base
    const int cbase = nwarp + (lane & 3) * 2;
    const int tile  = blockIdx.x * 2 + wn;
    const int mode  = g_labmode;

    #pragma unroll
    for (int mi = 0; mi < 2; mi++) {
        #pragma unroll
        for (int off = 0; off < 2; off++) {
            const int row = m0 + wm * 32 + quad + mi * 16 + off * 8;
            const int lab = mode ? l32[row] : l32[2 * row];

            float v[16];
            float mx = -FLT_MAX, ss = 0.f, sl = 0.f;
            #pragma unroll
            for (int ni = 0; ni < 8; ni++) {
                #pragma unroll
                for (int b = 0; b < 2; b++) {
                    const int col = cbase + ni * 8 + b;
                    const float val = 2.f * acc[mi][ni][off * 2 + b];
                    const bool ok = (col < NCLS);
                    v[ni * 2 + b] = ok ? val : -FLT_MAX;
                    if (ok) { mx = fmaxf(mx, val); ss += val; }
                    if (col == lab) sl = val;
                }
            }
            // quad max
            mx = fmaxf(mx, __shfl_xor_sync(0xFFFFFFFFu, mx, 1));
            mx = fmaxf(mx, __shfl_xor_sync(0xFFFFFFFFu, mx, 2));
            // sumexp with quad max
            float se = 0.f;
            #pragma unroll
            for (int j = 0; j < 16; j++)
                if (v[j] > -FLT_MAX) se += __expf(v[j] - mx);
            // quad sums
            se += __shfl_xor_sync(0xFFFFFFFFu, se, 1);
            se += __shfl_xor_sync(0xFFFFFFFFu, se, 2);
            ss += __shfl_xor_sync(0xFFFFFFFFu, ss, 1);
            ss += __shfl_xor_sync(0xFFFFFFFFu, ss, 2);
            sl += __shfl_xor_sync(0xFFFFFFFFu, sl, 1);
            sl += __shfl_xor_sync(0xFFFFFFFFu, sl, 2);

            if ((lane & 3) == 0)
                g_part[tile][row] = make_float4(mx, se, ss, sl);
        }
    }
}

// ---------------------------------------------------------------- combine
__global__ void combine_kernel() {
    const int row = blockIdx.x * blockDim.x + threadIdx.x;
    if (row >= B_ROWS) return;

    float4 p[NTILES];
    #pragma unroll
    for (int t = 0; t < NTILES; t++) p[t] = g_part[t][row];

    float m = -FLT_MAX;
    #pragma unroll
    for (int t = 0; t < NTILES; t++) m = fmaxf(m, p[t].x);

    float se = 0.f, ss = 0.f, sl = 0.f;
    #pragma unroll
    for (int t = 0; t < NTILES; t++) {
        se += p[t].y * __expf(p[t].x - m);
        ss += p[t].z;
        sl += p[t].w;
    }
    g_row[row] = m + logf(se) - (EPS / (float)NCLS) * ss - (1.0f - EPS) * sl;
}

// ---------------------------------------------------------------- finalize
__global__ void finalize_kernel(float* __restrict__ out) {
    __shared__ float warp_sums[8];
    float s = 0.f;
    for (int i = threadIdx.x; i < B_ROWS; i += 256)
        s += g_row[i];
    #pragma unroll
    for (int off = 16; off > 0; off >>= 1)
        s += __shfl_xor_sync(0xFFFFFFFFu, s, off);
    if ((threadIdx.x & 31) == 0) warp_sums[threadIdx.x >> 5] = s;
    __syncthreads();
    if (threadIdx.x == 0) {
        float t = 0.f;
        #pragma unroll
        for (int w = 0; w < 8; w++) t += warp_sums[w];
        out[0] = t / (float)B_ROWS;
    }
}

// ----------------------------------------------------------------------------
extern "C" void kernel_launch(void* const* d_in, const int* in_sizes, int n_in,
                              void* d_out, int out_size) {
    const float* A   = (const float*)d_in[0];   // inputs [16384, 1000]
    const int*   lab = (const int*)d_in[1];     // labels (dtype auto-detected)
    const float* Cb  = (const float*)d_in[2];   // code_book [1000, 1000]
    float* out = (float*)d_out;

    cudaFuncSetAttribute(gemm_kernel,
                         cudaFuncAttributeMaxDynamicSharedMemorySize, SMEM_TOTAL);

    detect_kernel<<<1, 256>>>(lab);
    convA_kernel<<<B_ROWS * 128 / 256, 256>>>(A);
    convC_kernel<<<1024 * 128 / 256, 256>>>(Cb);
    gemm_kernel<<<dim3(1024 / BN, B_ROWS / BM), 256, SMEM_TOTAL>>>(lab);
    combine_kernel<<<B_ROWS / 256, 256>>>();
    finalize_kernel<<<1, 256>>>(out);
}